// round 14
// baseline (speedup 1.0000x reference)
#include <cuda_runtime.h>
#include <math.h>

// Problem constants (fixed by reference)
#define B_   8
#define T_   4096
#define D_   64
#define R_   64
#define BT_  (B_ * T_)           // 32768 tokens
#define STRENGTH 0.1f
#define PHI_SCALE 0.17677669529663689f   // sqrt(2/64)
#define K1BLK 256                 // K1 blocks, 128 tokens each
#define WPAD 68                   // padded row stride (floats): 16B-aligned rows

// Scratch (static device globals — allocation-free)
__device__ float g_phi[BT_ * R_];          // 8 MB
__device__ float g_part[K1BLK * R_];       // per-block phi_sum partials
__device__ float g_phisum[B_ * R_];        // 2 KB

typedef unsigned long long u64;

__device__ __forceinline__ void unpack2(u64 v, float& lo, float& hi) {
    unsigned a, b;
    asm("mov.b64 {%0, %1}, %2;" : "=r"(a), "=r"(b) : "l"(v));
    lo = __uint_as_float(a); hi = __uint_as_float(b);
}
__device__ __forceinline__ u64 ffma2(u64 a, u64 b, u64 c) {
    u64 d;
    asm("fma.rn.f32x2 %0, %1, %2, %3;" : "=l"(d) : "l"(a), "l"(b), "l"(c));
    return d;
}

// ---------------------------------------------------------------------------
// K1: thread = token. Warp walks outputs together, so ALL weight reads are
// broadcast LDS.128 (1 crossbar phase). Coords live in registers as natural
// (c_d, c_{d+1}) u64 pairs from LDG.128 — zero packing MOVs.
// grid = 256 x 128 threads (4 warps), 128 tokens per block.
// ---------------------------------------------------------------------------
__global__ __launch_bounds__(128)
void k1_phi_mass(const float* __restrict__ coords,
                 const float* __restrict__ w1, const float* __restrict__ b1,
                 const float* __restrict__ w2, const float* __restrict__ b2,
                 const float* __restrict__ W,  const float* __restrict__ b)
{
    __shared__ __align__(16) float Wt[R_ * WPAD];   // Wt[r][d] = W[d][r]  (17.4KB)
    __shared__ __align__(16) float Ht[D_ * WPAD];   // Ht[j][d] = w1[j][d] (17.4KB)
    __shared__ float bsh[R_], b1sh[D_], w2sh[D_];
    __shared__ float psum[4][R_];

    const int tid  = threadIdx.x;
    const int wid  = tid >> 5;          // 0..3
    const int lane = tid & 31;
    const int tok  = blockIdx.x * 128 + tid;

    // ---- stage weights ----
    for (int i = tid; i < D_ * R_; i += 128) {
        const int d = i >> 6, r = i & 63;
        Wt[r * WPAD + d] = W[i];        // transpose: 4-way bank conflict, tiny
    }
    for (int i = tid; i < D_ * D_; i += 128) {
        const int j = i >> 6, d = i & 63;
        Ht[j * WPAD + d] = w1[i];       // already output-major: conflict-free
    }
    if (tid < 64) { bsh[tid] = b[tid]; b1sh[tid] = b1[tid]; w2sh[tid] = w2[tid]; }
    const float b2v = b2[0];

    // ---- coords for this thread's token: 16 x LDG.128 -> 32 u64 pairs ----
    ulonglong2 cc[16];
    {
        const ulonglong2* csrc = (const ulonglong2*)(coords + (size_t)tok * D_);
        #pragma unroll
        for (int i = 0; i < 16; ++i) cc[i] = __ldg(&csrc[i]);
    }
    __syncthreads();

    // ================= mass-net: h = relu(c@w1^T + b1); mass = softplus =====
    float macc = 0.0f;
    #pragma unroll 1
    for (int g = 0; g < 16; ++g) {
        const int j0 = g * 4;
        u64 a0 = 0, a1 = 0, a2 = 0, a3 = 0;
        #pragma unroll
        for (int d4 = 0; d4 < 16; ++d4) {
            const ulonglong2 w0 = *(const ulonglong2*)&Ht[(j0    ) * WPAD + d4 * 4];
            const ulonglong2 w1r = *(const ulonglong2*)&Ht[(j0 + 1) * WPAD + d4 * 4];
            const ulonglong2 w2r = *(const ulonglong2*)&Ht[(j0 + 2) * WPAD + d4 * 4];
            const ulonglong2 w3r = *(const ulonglong2*)&Ht[(j0 + 3) * WPAD + d4 * 4];
            const u64 ca = cc[d4].x, cb = cc[d4].y;
            a0 = ffma2(ca, w0.x,  a0); a0 = ffma2(cb, w0.y,  a0);
            a1 = ffma2(ca, w1r.x, a1); a1 = ffma2(cb, w1r.y, a1);
            a2 = ffma2(ca, w2r.x, a2); a2 = ffma2(cb, w2r.y, a2);
            a3 = ffma2(ca, w3r.x, a3); a3 = ffma2(cb, w3r.y, a3);
        }
        const float4 b1v = *(const float4*)&b1sh[j0];
        const float4 w2v = *(const float4*)&w2sh[j0];
        float lo, hi;
        unpack2(a0, lo, hi); macc = fmaf(fmaxf(lo + hi + b1v.x, 0.0f), w2v.x, macc);
        unpack2(a1, lo, hi); macc = fmaf(fmaxf(lo + hi + b1v.y, 0.0f), w2v.y, macc);
        unpack2(a2, lo, hi); macc = fmaf(fmaxf(lo + hi + b1v.z, 0.0f), w2v.z, macc);
        unpack2(a3, lo, hi); macc = fmaf(fmaxf(lo + hi + b1v.w, 0.0f), w2v.w, macc);
    }
    const float x = macc + b2v;
    const float mass = fmaxf(x, 0.0f) + log1pf(expf(-fabsf(x)));  // stable softplus

    // ================= RFF: phi = scale*cos(c@W + b); psum += phi*mass ======
    #pragma unroll 1
    for (int g = 0; g < 16; ++g) {
        const int r0 = g * 4;
        u64 a0 = 0, a1 = 0, a2 = 0, a3 = 0;
        #pragma unroll
        for (int d4 = 0; d4 < 16; ++d4) {
            const ulonglong2 w0 = *(const ulonglong2*)&Wt[(r0    ) * WPAD + d4 * 4];
            const ulonglong2 w1r = *(const ulonglong2*)&Wt[(r0 + 1) * WPAD + d4 * 4];
            const ulonglong2 w2r = *(const ulonglong2*)&Wt[(r0 + 2) * WPAD + d4 * 4];
            const ulonglong2 w3r = *(const ulonglong2*)&Wt[(r0 + 3) * WPAD + d4 * 4];
            const u64 ca = cc[d4].x, cb = cc[d4].y;
            a0 = ffma2(ca, w0.x,  a0); a0 = ffma2(cb, w0.y,  a0);
            a1 = ffma2(ca, w1r.x, a1); a1 = ffma2(cb, w1r.y, a1);
            a2 = ffma2(ca, w2r.x, a2); a2 = ffma2(cb, w2r.y, a2);
            a3 = ffma2(ca, w3r.x, a3); a3 = ffma2(cb, w3r.y, a3);
        }
        const float4 bv = *(const float4*)&bsh[r0];
        float lo, hi;
        float4 ph;
        unpack2(a0, lo, hi); ph.x = PHI_SCALE * __cosf(lo + hi + bv.x);
        unpack2(a1, lo, hi); ph.y = PHI_SCALE * __cosf(lo + hi + bv.y);
        unpack2(a2, lo, hi); ph.z = PHI_SCALE * __cosf(lo + hi + bv.z);
        unpack2(a3, lo, hi); ph.w = PHI_SCALE * __cosf(lo + hi + bv.w);
        *(float4*)&g_phi[(size_t)tok * R_ + r0] = ph;   // scattered STG.128

        // phi*mass, warp-reduced (fixed order -> deterministic)
        float p0 = ph.x * mass, p1 = ph.y * mass, p2 = ph.z * mass, p3 = ph.w * mass;
        #pragma unroll
        for (int off = 16; off > 0; off >>= 1) {
            p0 += __shfl_xor_sync(0xffffffffu, p0, off);
            p1 += __shfl_xor_sync(0xffffffffu, p1, off);
            p2 += __shfl_xor_sync(0xffffffffu, p2, off);
            p3 += __shfl_xor_sync(0xffffffffu, p3, off);
        }
        if (lane == 0) *(float4*)&psum[wid][r0] = make_float4(p0, p1, p2, p3);
    }
    __syncthreads();
    if (tid < 64)
        g_part[blockIdx.x * R_ + tid] =
            psum[0][tid] + psum[1][tid] + psum[2][tid] + psum[3][tid];
}

// ---------------------------------------------------------------------------
// K2: reduce 32 block-partials per (batch, r) in fixed order. <<<8, 64>>>
// (blocks per batch = 4096 tokens / 128 tokens-per-block = 32)
// ---------------------------------------------------------------------------
__global__ void k2_reduce_phisum()
{
    const int batch = blockIdx.x;
    const int r = threadIdx.x;
    float s = 0.0f;
    #pragma unroll 8
    for (int c = 0; c < 32; ++c)
        s += g_part[(batch * 32 + c) * R_ + r];
    g_phisum[batch * R_ + r] = s;
}

// ---------------------------------------------------------------------------
// K4: grav (warp 0) + streaming copy of G with diagonal add.
// Block per token (32768 blocks), 256 threads — unchanged (86% DRAM, proven).
// ---------------------------------------------------------------------------
__global__ __launch_bounds__(256)
void k4_copy(const float4* __restrict__ G4, float4* __restrict__ out4)
{
    const int tok = blockIdx.x;
    __shared__ float gsh;

    if (threadIdx.x < 32) {
        const int lane = threadIdx.x;
        const int batch = tok >> 12;                 // T = 4096
        const float* ph = g_phi    + (size_t)tok * R_;
        const float* ps = g_phisum + batch * R_;
        float s = ph[lane] * ps[lane] + ph[lane + 32] * ps[lane + 32];
        #pragma unroll
        for (int off = 16; off > 0; off >>= 1)
            s += __shfl_down_sync(0xffffffffu, s, off);
        if (lane == 0) gsh = STRENGTH * s;
    }
    __syncthreads();
    const float g = gsh;

    const float4* src = G4   + (size_t)tok * 1024;   // 4096 floats
    float4*       dst = out4 + (size_t)tok * 1024;

    float4 v[4];
    #pragma unroll
    for (int i = 0; i < 4; ++i)
        v[i] = __ldcs(&src[threadIdx.x + i * 256]);  // batched streaming loads

    #pragma unroll
    for (int i = 0; i < 4; ++i) {
        const int idx = threadIdx.x + i * 256;
        const int lin = idx << 2;
        float4 x = v[i];
        if (((lin    ) >> 6) == ((lin    ) & 63)) x.x += g;
        if (((lin + 1) >> 6) == ((lin + 1) & 63)) x.y += g;
        if (((lin + 2) >> 6) == ((lin + 2) & 63)) x.z += g;
        if (((lin + 3) >> 6) == ((lin + 3) & 63)) x.w += g;
        __stcs(&dst[idx], x);                        // streaming stores
    }
}

// ---------------------------------------------------------------------------
extern "C" void kernel_launch(void* const* d_in, const int* in_sizes, int n_in,
                              void* d_out, int out_size)
{
    const float* G      = (const float*)d_in[0];
    const float* coords = (const float*)d_in[1];
    const float* w1     = (const float*)d_in[2];
    const float* b1     = (const float*)d_in[3];
    const float* w2     = (const float*)d_in[4];
    const float* b2     = (const float*)d_in[5];
    const float* W      = (const float*)d_in[6];
    const float* b      = (const float*)d_in[7];
    float* out = (float*)d_out;

    k1_phi_mass<<<K1BLK, 128>>>(coords, w1, b1, w2, b2, W, b);
    k2_reduce_phisum<<<8, 64>>>();
    k4_copy<<<BT_, 256>>>((const float4*)G, (float4*)out);
}